// round 1
// baseline (speedup 1.0000x reference)
#include <cuda_runtime.h>
#include <cstdint>
#include <cstddef>

// Problem shape (fixed by the dataset)
constexpr int Bb  = 128;
constexpr int Nn  = 256;
constexpr int Cch = 512;
constexpr int Oo  = 256;
constexpr int MR  = Bb * Nn;      // 32768 rows for the flattened GEMMs
constexpr int C3  = 3 * Cch;      // 1536

// Scratch in __device__ globals (allocation-free rule)
__device__ float g_msg [MR * Cch];        //  64 MB
__device__ float g_gx  [(size_t)MR * C3]; // 201 MB
__device__ float g_gh  [(size_t)MR * C3]; // 201 MB
__device__ float g_hnew[MR * Cch];        //  64 MB

__device__ __forceinline__ uint32_t f2tf(float f) {
    uint32_t u;
    asm("cvt.rna.tf32.f32 %0, %1;" : "=r"(u) : "f"(f));
    return u;
}

__device__ __forceinline__ void mma8(float* c, const uint32_t* a, const uint32_t* b) {
    asm volatile(
        "mma.sync.aligned.m16n8k8.row.col.f32.tf32.tf32.f32 "
        "{%0,%1,%2,%3}, {%4,%5,%6,%7}, {%8,%9}, {%0,%1,%2,%3};\n"
        : "+f"(c[0]), "+f"(c[1]), "+f"(c[2]), "+f"(c[3])
        : "r"(a[0]), "r"(a[1]), "r"(a[2]), "r"(a[3]),
          "r"(b[0]), "r"(b[1]));
}

// ---------------------------------------------------------------------------
// TF32 GEMM: C[M,N] = A[M,K] (row-major) @ B[K,N] (row-major) + bias[N]
// CTA tile 128x128, 8 warps (2x4), warp tile 64x32, BK=16, double-buffered.
// All of M,N multiples of 128 and K multiple of 16 (holds for every call).
// ---------------------------------------------------------------------------
constexpr int BM = 128, BN = 128, BK = 16;
constexpr int ASTR = BK + 4;   // 20  -> A-frag LDS conflict-free (perm of banks)
constexpr int BSTR = BN + 8;   // 136 -> B-frag LDS conflict-free

__global__ __launch_bounds__(256, 1)
void gemm_tf32(const float* __restrict__ A, const float* __restrict__ B,
               float* __restrict__ C, const float* __restrict__ bias,
               int K, int lda, int ldb, int ldc,
               long long sA, long long sB, long long sC)
{
    __shared__ uint32_t As[2][BM * ASTR];  // 20480 B
    __shared__ uint32_t Bs[2][BK * BSTR];  // 17408 B  (total 37888 B < 48K)

    A += (long long)blockIdx.z * sA;
    B += (long long)blockIdx.z * sB;
    C += (long long)blockIdx.z * sC;

    const int tid  = threadIdx.x;
    const int lane = tid & 31;
    const int warp = tid >> 5;
    const int wm   = warp >> 2;                 // 0..1  (M dir)
    const int wn   = warp & 3;                  // 0..3  (N dir)
    const int row0 = blockIdx.y * BM;
    const int col0 = blockIdx.x * BN;

    // global -> smem tile mapping (float4 loads)
    const int arow = tid >> 2;                  // 0..63  (+64 second half)
    const int acol = (tid & 3) * 4;             // 0,4,8,12
    const int brow = tid >> 5;                  // 0..7   (+8 second half)
    const int bcol = (tid & 31) * 4;            // 0..124

    const float* aP = A + (size_t)(row0 + arow) * lda + acol;
    const float* bP = B + (size_t)brow * ldb + (col0 + bcol);

    const int ktiles = K / BK;

    float acc[4][4][4];
#pragma unroll
    for (int mi = 0; mi < 4; mi++)
#pragma unroll
        for (int ni = 0; ni < 4; ni++)
#pragma unroll
            for (int r = 0; r < 4; r++) acc[mi][ni][r] = 0.f;

    // prologue: tile 0 -> smem buf 0
    {
        float4 a0 = *(const float4*)(aP);
        float4 a1 = *(const float4*)(aP + (size_t)64 * lda);
        float4 b0 = *(const float4*)(bP);
        float4 b1 = *(const float4*)(bP + (size_t)8 * ldb);
        uint32_t* p;
        p = &As[0][arow * ASTR + acol];
        p[0]=f2tf(a0.x); p[1]=f2tf(a0.y); p[2]=f2tf(a0.z); p[3]=f2tf(a0.w);
        p = &As[0][(arow + 64) * ASTR + acol];
        p[0]=f2tf(a1.x); p[1]=f2tf(a1.y); p[2]=f2tf(a1.z); p[3]=f2tf(a1.w);
        p = &Bs[0][brow * BSTR + bcol];
        p[0]=f2tf(b0.x); p[1]=f2tf(b0.y); p[2]=f2tf(b0.z); p[3]=f2tf(b0.w);
        p = &Bs[0][(brow + 8) * BSTR + bcol];
        p[0]=f2tf(b1.x); p[1]=f2tf(b1.y); p[2]=f2tf(b1.z); p[3]=f2tf(b1.w);
    }
    __syncthreads();

    for (int kt = 0; kt < ktiles; kt++) {
        const int cur = kt & 1;
        const bool hasNext = (kt + 1) < ktiles;

        float4 a0, a1, b0, b1;
        if (hasNext) {  // prefetch next tile into registers (overlaps compute)
            const float* ap = aP + (size_t)(kt + 1) * BK;
            a0 = *(const float4*)(ap);
            a1 = *(const float4*)(ap + (size_t)64 * lda);
            const float* bp = bP + (size_t)(kt + 1) * BK * ldb;
            b0 = *(const float4*)(bp);
            b1 = *(const float4*)(bp + (size_t)8 * ldb);
        }

#pragma unroll
        for (int kk = 0; kk < BK; kk += 8) {
            uint32_t af[4][4], bf[4][2];
#pragma unroll
            for (int mi = 0; mi < 4; mi++) {
                const int r  = wm * 64 + mi * 16 + (lane >> 2);
                const int cc = kk + (lane & 3);
                af[mi][0] = As[cur][ r      * ASTR + cc    ];
                af[mi][1] = As[cur][(r + 8) * ASTR + cc    ];
                af[mi][2] = As[cur][ r      * ASTR + cc + 4];
                af[mi][3] = As[cur][(r + 8) * ASTR + cc + 4];
            }
#pragma unroll
            for (int ni = 0; ni < 4; ni++) {
                const int cc = wn * 32 + ni * 8 + (lane >> 2);
                const int kr = kk + (lane & 3);
                bf[ni][0] = Bs[cur][ kr      * BSTR + cc];
                bf[ni][1] = Bs[cur][(kr + 4) * BSTR + cc];
            }
#pragma unroll
            for (int mi = 0; mi < 4; mi++)
#pragma unroll
                for (int ni = 0; ni < 4; ni++)
                    mma8(acc[mi][ni], af[mi], bf[ni]);
        }

        __syncthreads();
        if (hasNext) {
            const int nxt = cur ^ 1;
            uint32_t* p;
            p = &As[nxt][arow * ASTR + acol];
            p[0]=f2tf(a0.x); p[1]=f2tf(a0.y); p[2]=f2tf(a0.z); p[3]=f2tf(a0.w);
            p = &As[nxt][(arow + 64) * ASTR + acol];
            p[0]=f2tf(a1.x); p[1]=f2tf(a1.y); p[2]=f2tf(a1.z); p[3]=f2tf(a1.w);
            p = &Bs[nxt][brow * BSTR + bcol];
            p[0]=f2tf(b0.x); p[1]=f2tf(b0.y); p[2]=f2tf(b0.z); p[3]=f2tf(b0.w);
            p = &Bs[nxt][(brow + 8) * BSTR + bcol];
            p[0]=f2tf(b1.x); p[1]=f2tf(b1.y); p[2]=f2tf(b1.z); p[3]=f2tf(b1.w);
            __syncthreads();
        }
    }

    // epilogue: bias add + store (float2, coalesced pairs per accum tile)
#pragma unroll
    for (int mi = 0; mi < 4; mi++) {
        const int gr = row0 + wm * 64 + mi * 16 + (lane >> 2);
#pragma unroll
        for (int ni = 0; ni < 4; ni++) {
            const int gc = col0 + wn * 32 + ni * 8 + (lane & 3) * 2;
            const float bv0 = bias[gc];
            const float bv1 = bias[gc + 1];
            float2 v0 = make_float2(acc[mi][ni][0] + bv0, acc[mi][ni][1] + bv1);
            float2 v1 = make_float2(acc[mi][ni][2] + bv0, acc[mi][ni][3] + bv1);
            *(float2*)&C[(size_t) gr      * ldc + gc] = v0;
            *(float2*)&C[(size_t)(gr + 8) * ldc + gc] = v1;
        }
    }
}

// ---------------------------------------------------------------------------
// GRU gate fusion: hnew = z*h + (1-z)*tanh(xh + r*hh),  z/r = sigmoid(.+.)
// ---------------------------------------------------------------------------
__device__ __forceinline__ float gate1(float xz, float hz, float xr, float hr,
                                       float xh, float hh, float h) {
    const float z = 1.f / (1.f + __expf(-(xz + hz)));
    const float r = 1.f / (1.f + __expf(-(xr + hr)));
    const float hc = tanhf(xh + r * hh);
    return z * h + (1.f - z) * hc;
}

__global__ __launch_bounds__(256)
void gates_kernel(const float* __restrict__ ann)
{
    const int i   = blockIdx.x * blockDim.x + threadIdx.x;  // float4 index
    const int row = i >> 7;                                  // Cch/4 = 128
    const int j   = (i & 127) * 4;
    const size_t bx = (size_t)row * C3 + j;
    const float4 xz = *(const float4*)&g_gx[bx];
    const float4 xr = *(const float4*)&g_gx[bx + Cch];
    const float4 xh = *(const float4*)&g_gx[bx + 2 * Cch];
    const float4 hz = *(const float4*)&g_gh[bx];
    const float4 hr = *(const float4*)&g_gh[bx + Cch];
    const float4 hh = *(const float4*)&g_gh[bx + 2 * Cch];
    const float4 h  = *(const float4*)&ann[(size_t)row * Cch + j];
    float4 o;
    o.x = gate1(xz.x, hz.x, xr.x, hr.x, xh.x, hh.x, h.x);
    o.y = gate1(xz.y, hz.y, xr.y, hr.y, xh.y, hh.y, h.y);
    o.z = gate1(xz.z, hz.z, xr.z, hr.z, xh.z, hh.z, h.z);
    o.w = gate1(xz.w, hz.w, xr.w, hr.w, xh.w, hh.w, h.w);
    *(float4*)&g_hnew[(size_t)row * Cch + j] = o;
}

// ---------------------------------------------------------------------------
// Launch: bmm -> (gx, gh) -> gates -> dense
// ---------------------------------------------------------------------------
extern "C" void kernel_launch(void* const* d_in, const int* in_sizes, int n_in,
                              void* d_out, int out_size)
{
    const float* adj = (const float*)d_in[0];  // [B, N, N]
    const float* ann = (const float*)d_in[1];  // [B, N, C]
    const float* gcb = (const float*)d_in[2];  // [1, 1, C]
    const float* W   = (const float*)d_in[3];  // [C, 3C]
    const float* U   = (const float*)d_in[4];  // [C, 3C]
    const float* gb  = (const float*)d_in[5];  // [2, 3C]
    const float* dW  = (const float*)d_in[6];  // [C, O]
    const float* db  = (const float*)d_in[7];  // [O]
    float* out = (float*)d_out;

    float *msg, *gx, *gh, *hnew;
    cudaGetSymbolAddress((void**)&msg,  g_msg);
    cudaGetSymbolAddress((void**)&gx,   g_gx);
    cudaGetSymbolAddress((void**)&gh,   g_gh);
    cudaGetSymbolAddress((void**)&hnew, g_hnew);

    const dim3 blk(256);

    // 1) msg = bmm(adjacent, annotations) + gc_bias   (batched: z = batch)
    gemm_tf32<<<dim3(Cch / BN, Nn / BM, Bb), blk>>>(
        adj, ann, msg, gcb,
        /*K=*/Nn, /*lda=*/Nn, /*ldb=*/Cch, /*ldc=*/Cch,
        (long long)Nn * Nn, (long long)Nn * Cch, (long long)Nn * Cch);

    // 2a) gx = msg @ gru_W + gru_b[0]
    gemm_tf32<<<dim3(C3 / BN, MR / BM, 1), blk>>>(
        msg, W, gx, gb,
        /*K=*/Cch, /*lda=*/Cch, /*ldb=*/C3, /*ldc=*/C3, 0, 0, 0);

    // 2b) gh = annotations @ gru_U + gru_b[1]
    gemm_tf32<<<dim3(C3 / BN, MR / BM, 1), blk>>>(
        ann, U, gh, gb + C3,
        /*K=*/Cch, /*lda=*/Cch, /*ldb=*/C3, /*ldc=*/C3, 0, 0, 0);

    // 3) gate fusion -> hnew
    gates_kernel<<<(MR * (Cch / 4)) / 256, blk>>>(ann);

    // 4) out = hnew @ dense_W + dense_b
    gemm_tf32<<<dim3(Oo / BN, MR / BM, 1), blk>>>(
        hnew, dW, out, db,
        /*K=*/Cch, /*lda=*/Cch, /*ldb=*/Oo, /*ldc=*/Oo, 0, 0, 0);
}

// round 4
// speedup vs baseline: 1.3584x; 1.3584x over previous
#include <cuda_runtime.h>
#include <cstdint>
#include <cstddef>

// ---------------------------------------------------------------- shapes
constexpr int Bb  = 128;
constexpr int Nn  = 256;
constexpr int Cch = 512;
constexpr int Oo  = 256;
constexpr int MR  = Bb * Nn;   // 32768
constexpr int C3  = 3 * Cch;   // 1536

// ---------------------------------------------------------------- scratch
__device__ float g_msg [(size_t)MR * Cch];
__device__ float g_gx  [(size_t)MR * C3];
__device__ float g_gh  [(size_t)MR * C3];
__device__ float g_hnew[(size_t)MR * Cch];

// ---------------------------------------------------------------- helpers
__device__ __forceinline__ uint32_t smem_u32(const void* p) {
    uint32_t a;
    asm("{ .reg .u64 t; cvta.to.shared.u64 t, %1; cvt.u32.u64 %0, t; }" : "=r"(a) : "l"(p));
    return a;
}
__device__ __forceinline__ uint32_t f2tf(float f) {
    uint32_t u;
    asm("cvt.rna.tf32.f32 %0, %1;" : "=r"(u) : "f"(f));
    return u;
}
__device__ __forceinline__ void cp16(uint32_t saddr, const float* g) {
    asm volatile("cp.async.cg.shared.global [%0], [%1], 16;" :: "r"(saddr), "l"(g));
}
#define CP_COMMIT() asm volatile("cp.async.commit_group;" ::: "memory")
#define CP_WAIT2()  asm volatile("cp.async.wait_group 2;"  ::: "memory")

__device__ __forceinline__ void mma8(float* c, const uint32_t* a, const uint32_t* b) {
    asm volatile(
        "mma.sync.aligned.m16n8k8.row.col.f32.tf32.tf32.f32 "
        "{%0,%1,%2,%3}, {%4,%5,%6,%7}, {%8,%9}, {%0,%1,%2,%3};\n"
        : "+f"(c[0]), "+f"(c[1]), "+f"(c[2]), "+f"(c[3])
        : "r"(a[0]), "r"(a[1]), "r"(a[2]), "r"(a[3]),
          "r"(b[0]), "r"(b[1]));
}

// ---------------------------------------------------------------- GEMM
// C[M,N] = A[M,K](row) @ B[K,N](row) + bias[N]
// CTA 128x128, 8 warps (2x4), warp 64x32, BK=16, 4-stage cp.async pipeline.
constexpr int BM = 128, BN = 128, BK = 16;
constexpr int ASTR = BK + 4;    // 20 floats; 80B/row -> 16B-aligned chunks
constexpr int BSTR = BN + 8;    // 136 floats; 544B/row -> 16B-aligned chunks
constexpr int STAGES = 4;
constexpr int ASZ = BM * ASTR;  // 2560 floats / stage
constexpr int BSZ = BK * BSTR;  // 2176 floats / stage
constexpr int SMEM_FLOATS = STAGES * (ASZ + BSZ);           // 18944
constexpr int SMEM_BYTES  = SMEM_FLOATS * 4;                // 75776 B

__global__ __launch_bounds__(256, 1)
void gemm_tf32(const float* __restrict__ A, const float* __restrict__ B,
               float* __restrict__ C, const float* __restrict__ bias,
               int K, int lda, int ldb, int ldc,
               long long sA, long long sB, long long sC)
{
    extern __shared__ float sm[];
    float* As = sm;                    // [STAGES][ASZ]
    float* Bs = sm + STAGES * ASZ;     // [STAGES][BSZ]
    const uint32_t sbA = smem_u32(As);
    const uint32_t sbB = smem_u32(Bs);

    A += (long long)blockIdx.z * sA;
    B += (long long)blockIdx.z * sB;
    C += (long long)blockIdx.z * sC;

    const int tid  = threadIdx.x;
    const int lane = tid & 31;
    const int warp = tid >> 5;
    const int wm   = warp >> 2;           // 0..1
    const int wn   = warp & 3;            // 0..3
    const int row0 = blockIdx.y * BM;
    const int col0 = blockIdx.x * BN;

    // cp.async tile mapping (16B chunks)
    const int arow = tid >> 2;            // 0..63 (+64)
    const int acol = (tid & 3) * 4;       // 0,4,8,12
    const int brow = tid >> 5;            // 0..7  (+8)
    const int bcol = (tid & 31) * 4;      // 0..124

    const float* aG = A + (size_t)(row0 + arow) * lda + acol;
    const float* bG = B + (size_t)brow * ldb + (col0 + bcol);
    const uint32_t aS0 = sbA + (uint32_t)(arow * ASTR + acol) * 4u;
    const uint32_t aS1 = sbA + (uint32_t)((arow + 64) * ASTR + acol) * 4u;
    const uint32_t bS0 = sbB + (uint32_t)(brow * BSTR + bcol) * 4u;
    const uint32_t bS1 = sbB + (uint32_t)((brow + 8) * BSTR + bcol) * 4u;

    auto issue = [&](int kt, int s) {
        const float* ag = aG + (size_t)kt * BK;
        cp16(aS0 + s * (ASZ * 4), ag);
        cp16(aS1 + s * (ASZ * 4), ag + (size_t)64 * lda);
        const float* bg = bG + (size_t)kt * BK * ldb;
        cp16(bS0 + s * (BSZ * 4), bg);
        cp16(bS1 + s * (BSZ * 4), bg + (size_t)8 * ldb);
    };

    const int T = K / BK;

    float acc[4][4][4];
#pragma unroll
    for (int mi = 0; mi < 4; mi++)
#pragma unroll
        for (int ni = 0; ni < 4; ni++)
#pragma unroll
            for (int r = 0; r < 4; r++) acc[mi][ni][r] = 0.f;

    // prologue: stages 0..STAGES-2
#pragma unroll
    for (int s = 0; s < STAGES - 1; s++) { issue(s, s); CP_COMMIT(); }

    for (int kt = 0; kt < T; kt++) {
        CP_WAIT2();
        __syncthreads();

        const int cs  = kt & (STAGES - 1);
        const int ktn = kt + STAGES - 1;
        if (ktn < T) issue(ktn, ktn & (STAGES - 1));
        CP_COMMIT();

        const float* as = As + cs * ASZ;
        const float* bs = Bs + cs * BSZ;
#pragma unroll
        for (int kk = 0; kk < BK; kk += 8) {
            uint32_t af[4][4], bf[4][2];
#pragma unroll
            for (int mi = 0; mi < 4; mi++) {
                const int r  = wm * 64 + mi * 16 + (lane >> 2);
                const int cc = kk + (lane & 3);
                af[mi][0] = f2tf(as[ r      * ASTR + cc    ]);
                af[mi][1] = f2tf(as[(r + 8) * ASTR + cc    ]);
                af[mi][2] = f2tf(as[ r      * ASTR + cc + 4]);
                af[mi][3] = f2tf(as[(r + 8) * ASTR + cc + 4]);
            }
#pragma unroll
            for (int ni = 0; ni < 4; ni++) {
                const int cc = wn * 32 + ni * 8 + (lane >> 2);
                const int kr = kk + (lane & 3);
                bf[ni][0] = f2tf(bs[ kr      * BSTR + cc]);
                bf[ni][1] = f2tf(bs[(kr + 4) * BSTR + cc]);
            }
#pragma unroll
            for (int mi = 0; mi < 4; mi++)
#pragma unroll
                for (int ni = 0; ni < 4; ni++)
                    mma8(acc[mi][ni], af[mi], bf[ni]);
        }
    }

    // epilogue: bias + store
#pragma unroll
    for (int mi = 0; mi < 4; mi++) {
        const int gr = row0 + wm * 64 + mi * 16 + (lane >> 2);
#pragma unroll
        for (int ni = 0; ni < 4; ni++) {
            const int gc = col0 + wn * 32 + ni * 8 + (lane & 3) * 2;
            const float bv0 = __ldg(&bias[gc]);
            const float bv1 = __ldg(&bias[gc + 1]);
            float2 v0 = make_float2(acc[mi][ni][0] + bv0, acc[mi][ni][1] + bv1);
            float2 v1 = make_float2(acc[mi][ni][2] + bv0, acc[mi][ni][3] + bv1);
            *(float2*)&C[(size_t) gr      * ldc + gc] = v0;
            *(float2*)&C[(size_t)(gr + 8) * ldc + gc] = v1;
        }
    }
}

// ---------------------------------------------------------------- gates
__device__ __forceinline__ float gate1(float xz, float hz, float xr, float hr,
                                       float xh, float hh, float h) {
    const float z = 1.f / (1.f + __expf(-(xz + hz)));
    const float r = 1.f / (1.f + __expf(-(xr + hr)));
    const float hc = tanhf(xh + r * hh);
    return z * h + (1.f - z) * hc;
}

__global__ __launch_bounds__(256)
void gates_kernel(const float* __restrict__ ann)
{
    const int i   = blockIdx.x * blockDim.x + threadIdx.x;
    const int row = i >> 7;
    const int j   = (i & 127) * 4;
    const size_t bx = (size_t)row * C3 + j;
    const float4 xz = *(const float4*)&g_gx[bx];
    const float4 xr = *(const float4*)&g_gx[bx + Cch];
    const float4 xh = *(const float4*)&g_gx[bx + 2 * Cch];
    const float4 hz = *(const float4*)&g_gh[bx];
    const float4 hr = *(const float4*)&g_gh[bx + Cch];
    const float4 hh = *(const float4*)&g_gh[bx + 2 * Cch];
    const float4 h  = *(const float4*)&ann[(size_t)row * Cch + j];
    float4 o;
    o.x = gate1(xz.x, hz.x, xr.x, hr.x, xh.x, hh.x, h.x);
    o.y = gate1(xz.y, hz.y, xr.y, hr.y, xh.y, hh.y, h.y);
    o.z = gate1(xz.z, hz.z, xr.z, hr.z, xh.z, hh.z, h.z);
    o.w = gate1(xz.w, hz.w, xr.w, hr.w, xh.w, hh.w, h.w);
    *(float4*)&g_hnew[(size_t)row * Cch + j] = o;
}

// ---------------------------------------------------------------- launch
extern "C" void kernel_launch(void* const* d_in, const int* in_sizes, int n_in,
                              void* d_out, int out_size)
{
    const float* adj = (const float*)d_in[0];
    const float* ann = (const float*)d_in[1];
    const float* gcb = (const float*)d_in[2];
    const float* W   = (const float*)d_in[3];
    const float* U   = (const float*)d_in[4];
    const float* gb  = (const float*)d_in[5];
    const float* dW  = (const float*)d_in[6];
    const float* db  = (const float*)d_in[7];
    float* out = (float*)d_out;

    float *msg, *gx, *gh, *hnew;
    cudaGetSymbolAddress((void**)&msg,  g_msg);
    cudaGetSymbolAddress((void**)&gx,   g_gx);
    cudaGetSymbolAddress((void**)&gh,   g_gh);
    cudaGetSymbolAddress((void**)&hnew, g_hnew);

    cudaFuncSetAttribute(gemm_tf32, cudaFuncAttributeMaxDynamicSharedMemorySize, SMEM_BYTES);

    const dim3 blk(256);

    // 1) msg = bmm(adjacent, annotations) + gc_bias
    gemm_tf32<<<dim3(Cch / BN, Nn / BM, Bb), blk, SMEM_BYTES>>>(
        adj, ann, msg, gcb,
        /*K=*/Nn, Nn, Cch, Cch,
        (long long)Nn * Nn, (long long)Nn * Cch, (long long)Nn * Cch);

    // 2a) gx = msg @ gru_W + gru_b[0]
    gemm_tf32<<<dim3(C3 / BN, MR / BM, 1), blk, SMEM_BYTES>>>(
        msg, W, gx, gb, Cch, Cch, C3, C3, 0, 0, 0);

    // 2b) gh = annotations @ gru_U + gru_b[1]
    gemm_tf32<<<dim3(C3 / BN, MR / BM, 1), blk, SMEM_BYTES>>>(
        ann, U, gh, gb + C3, Cch, Cch, C3, C3, 0, 0, 0);

    // 3) gates -> hnew
    gates_kernel<<<(MR * (Cch / 4)) / 256, blk>>>(ann);

    // 4) out = hnew @ dense_W + dense_b
    gemm_tf32<<<dim3(Oo / BN, MR / BM, 1), blk, SMEM_BYTES>>>(
        hnew, dW, out, db, Cch, Cch, Oo, Oo, 0, 0, 0);
}

// round 5
// speedup vs baseline: 1.4518x; 1.0688x over previous
#include <cuda_runtime.h>
#include <cstdint>
#include <cstddef>

// ---------------------------------------------------------------- shapes
constexpr int Bb  = 128;
constexpr int Nn  = 256;
constexpr int Cch = 512;
constexpr int Oo  = 256;
constexpr int MR  = Bb * Nn;   // 32768
constexpr int C3  = 3 * Cch;   // 1536

// ---------------------------------------------------------------- scratch
__device__ float g_msg [(size_t)MR * Cch];
__device__ float g_gx  [(size_t)MR * C3];
__device__ float g_gh  [(size_t)MR * C3];
__device__ float g_hnew[(size_t)MR * Cch];

// ---------------------------------------------------------------- helpers
__device__ __forceinline__ uint32_t smem_u32(const void* p) {
    uint32_t a;
    asm("{ .reg .u64 t; cvta.to.shared.u64 t, %1; cvt.u32.u64 %0, t; }" : "=r"(a) : "l"(p));
    return a;
}
__device__ __forceinline__ uint32_t f2tf(float f) {
    uint32_t u;
    asm("cvt.rna.tf32.f32 %0, %1;" : "=r"(u) : "f"(f));
    return u;
}
__device__ __forceinline__ void cp16(uint32_t saddr, const float* g) {
    asm volatile("cp.async.cg.shared.global [%0], [%1], 16;" :: "r"(saddr), "l"(g));
}
#define CP_COMMIT() asm volatile("cp.async.commit_group;" ::: "memory")
#define CP_WAIT1()  asm volatile("cp.async.wait_group 1;"  ::: "memory")

__device__ __forceinline__ void mma8(float* c, const uint32_t* a, const uint32_t* b) {
    asm volatile(
        "mma.sync.aligned.m16n8k8.row.col.f32.tf32.tf32.f32 "
        "{%0,%1,%2,%3}, {%4,%5,%6,%7}, {%8,%9}, {%0,%1,%2,%3};\n"
        : "+f"(c[0]), "+f"(c[1]), "+f"(c[2]), "+f"(c[3])
        : "r"(a[0]), "r"(a[1]), "r"(a[2]), "r"(a[3]),
          "r"(b[0]), "r"(b[1]));
}

// ---------------------------------------------------------------- GEMM
// C[M,N] = A[M,K](row) @ B[K,N](row) + bias[N]
// CTA 128x128, 8 warps (2x4), warp 64x32, BK=32, 3-stage cp.async, 2 CTA/SM.
constexpr int BM = 128, BN = 128, BK = 32;
constexpr int ASTR = BK + 4;    // 36 floats; 144B/row, 16B-aligned chunks
constexpr int BSTR = BN + 8;    // 136 floats; 544B/row
constexpr int STAGES = 3;
constexpr int ASZ = BM * ASTR;  // 4608 floats / stage
constexpr int BSZ = BK * BSTR;  // 4352 floats / stage
constexpr int SMEM_BYTES = STAGES * (ASZ + BSZ) * 4;   // 107520 B

__global__ __launch_bounds__(256, 2)
void gemm_tf32(const float* __restrict__ A, const float* __restrict__ B,
               float* __restrict__ C, const float* __restrict__ bias,
               int K, int lda, int ldb, int ldc,
               long long sA, long long sB, long long sC)
{
    extern __shared__ float sm[];
    float* As = sm;                    // [STAGES][ASZ]
    float* Bs = sm + STAGES * ASZ;     // [STAGES][BSZ]
    const uint32_t sbA = smem_u32(As);
    const uint32_t sbB = smem_u32(Bs);

    A += (long long)blockIdx.z * sA;
    B += (long long)blockIdx.z * sB;
    C += (long long)blockIdx.z * sC;

    const int tid  = threadIdx.x;
    const int lane = tid & 31;
    const int warp = tid >> 5;
    const int wm   = warp >> 2;           // 0..1
    const int wn   = warp & 3;            // 0..3
    const int row0 = blockIdx.y * BM;
    const int col0 = blockIdx.x * BN;

    // cp.async tile mapping (16B chunks)
    const int arow = tid >> 3;            // 0..31 (+32,+64,+96)
    const int acol = (tid & 7) * 4;       // 0..28
    const int brow = tid >> 5;            // 0..7  (+8,+16,+24)
    const int bcol = (tid & 31) * 4;      // 0..124

    const float* aG = A + (size_t)(row0 + arow) * lda + acol;
    const float* bG = B + (size_t)brow * ldb + (col0 + bcol);
    uint32_t aS[4], bS[4];
#pragma unroll
    for (int i = 0; i < 4; i++) {
        aS[i] = sbA + (uint32_t)((arow + 32 * i) * ASTR + acol) * 4u;
        bS[i] = sbB + (uint32_t)((brow + 8 * i) * BSTR + bcol) * 4u;
    }

    auto issue = [&](int kt, int s) {
        const float* ag = aG + (size_t)kt * BK;
        const float* bg = bG + (size_t)kt * BK * ldb;
#pragma unroll
        for (int i = 0; i < 4; i++)
            cp16(aS[i] + s * (ASZ * 4), ag + (size_t)(32 * i) * lda);
#pragma unroll
        for (int i = 0; i < 4; i++)
            cp16(bS[i] + s * (BSZ * 4), bg + (size_t)(8 * i) * ldb);
    };

    const int T = K / BK;

    float acc[4][4][4];
#pragma unroll
    for (int mi = 0; mi < 4; mi++)
#pragma unroll
        for (int ni = 0; ni < 4; ni++)
#pragma unroll
            for (int r = 0; r < 4; r++) acc[mi][ni][r] = 0.f;

    // prologue: stages 0,1
    issue(0, 0); CP_COMMIT();
    issue(1, 1); CP_COMMIT();

    int use_s = 0, fill_s = 2;
    for (int kt = 0; kt < T; kt++) {
        CP_WAIT1();
        __syncthreads();

        if (kt + 2 < T) issue(kt + 2, fill_s);
        CP_COMMIT();

        const float* as = As + use_s * ASZ;
        const float* bs = Bs + use_s * BSZ;
#pragma unroll
        for (int kk = 0; kk < BK; kk += 8) {
            uint32_t af[4][4], bf[4][2];
#pragma unroll
            for (int mi = 0; mi < 4; mi++) {
                const int r  = wm * 64 + mi * 16 + (lane >> 2);
                const int cc = kk + (lane & 3);
                af[mi][0] = f2tf(as[ r      * ASTR + cc    ]);
                af[mi][1] = f2tf(as[(r + 8) * ASTR + cc    ]);
                af[mi][2] = f2tf(as[ r      * ASTR + cc + 4]);
                af[mi][3] = f2tf(as[(r + 8) * ASTR + cc + 4]);
            }
#pragma unroll
            for (int ni = 0; ni < 4; ni++) {
                const int cc = wn * 32 + ni * 8 + (lane >> 2);
                const int kr = kk + (lane & 3);
                bf[ni][0] = f2tf(bs[ kr      * BSTR + cc]);
                bf[ni][1] = f2tf(bs[(kr + 4) * BSTR + cc]);
            }
#pragma unroll
            for (int mi = 0; mi < 4; mi++)
#pragma unroll
                for (int ni = 0; ni < 4; ni++)
                    mma8(acc[mi][ni], af[mi], bf[ni]);
        }

        if (++use_s  == STAGES) use_s  = 0;
        if (++fill_s == STAGES) fill_s = 0;
    }

    // epilogue: bias + store
#pragma unroll
    for (int mi = 0; mi < 4; mi++) {
        const int gr = row0 + wm * 64 + mi * 16 + (lane >> 2);
#pragma unroll
        for (int ni = 0; ni < 4; ni++) {
            const int gc = col0 + wn * 32 + ni * 8 + (lane & 3) * 2;
            const float bv0 = __ldg(&bias[gc]);
            const float bv1 = __ldg(&bias[gc + 1]);
            float2 v0 = make_float2(acc[mi][ni][0] + bv0, acc[mi][ni][1] + bv1);
            float2 v1 = make_float2(acc[mi][ni][2] + bv0, acc[mi][ni][3] + bv1);
            *(float2*)&C[(size_t) gr      * ldc + gc] = v0;
            *(float2*)&C[(size_t)(gr + 8) * ldc + gc] = v1;
        }
    }
}

// ---------------------------------------------------------------- gates
__device__ __forceinline__ float gate1(float xz, float hz, float xr, float hr,
                                       float xh, float hh, float h) {
    const float z = 1.f / (1.f + __expf(-(xz + hz)));
    const float r = 1.f / (1.f + __expf(-(xr + hr)));
    const float hc = tanhf(xh + r * hh);
    return z * h + (1.f - z) * hc;
}

__global__ __launch_bounds__(256)
void gates_kernel(const float* __restrict__ ann)
{
    const int i   = blockIdx.x * blockDim.x + threadIdx.x;
    const int row = i >> 7;
    const int j   = (i & 127) * 4;
    const size_t bx = (size_t)row * C3 + j;
    const float4 xz = *(const float4*)&g_gx[bx];
    const float4 xr = *(const float4*)&g_gx[bx + Cch];
    const float4 xh = *(const float4*)&g_gx[bx + 2 * Cch];
    const float4 hz = *(const float4*)&g_gh[bx];
    const float4 hr = *(const float4*)&g_gh[bx + Cch];
    const float4 hh = *(const float4*)&g_gh[bx + 2 * Cch];
    const float4 h  = *(const float4*)&ann[(size_t)row * Cch + j];
    float4 o;
    o.x = gate1(xz.x, hz.x, xr.x, hr.x, xh.x, hh.x, h.x);
    o.y = gate1(xz.y, hz.y, xr.y, hr.y, xh.y, hh.y, h.y);
    o.z = gate1(xz.z, hz.z, xr.z, hr.z, xh.z, hh.z, h.z);
    o.w = gate1(xz.w, hz.w, xr.w, hr.w, xh.w, hh.w, h.w);
    *(float4*)&g_hnew[(size_t)row * Cch + j] = o;
}

// ---------------------------------------------------------------- launch
extern "C" void kernel_launch(void* const* d_in, const int* in_sizes, int n_in,
                              void* d_out, int out_size)
{
    const float* adj = (const float*)d_in[0];
    const float* ann = (const float*)d_in[1];
    const float* gcb = (const float*)d_in[2];
    const float* W   = (const float*)d_in[3];
    const float* U   = (const float*)d_in[4];
    const float* gb  = (const float*)d_in[5];
    const float* dW  = (const float*)d_in[6];
    const float* db  = (const float*)d_in[7];
    float* out = (float*)d_out;

    float *msg, *gx, *gh, *hnew;
    cudaGetSymbolAddress((void**)&msg,  g_msg);
    cudaGetSymbolAddress((void**)&gx,   g_gx);
    cudaGetSymbolAddress((void**)&gh,   g_gh);
    cudaGetSymbolAddress((void**)&hnew, g_hnew);

    cudaFuncSetAttribute(gemm_tf32, cudaFuncAttributeMaxDynamicSharedMemorySize, SMEM_BYTES);

    const dim3 blk(256);

    // 1) msg = bmm(adjacent, annotations) + gc_bias   (K=256 -> T=8)
    gemm_tf32<<<dim3(Cch / BN, Nn / BM, Bb), blk, SMEM_BYTES>>>(
        adj, ann, msg, gcb,
        /*K=*/Nn, Nn, Cch, Cch,
        (long long)Nn * Nn, (long long)Nn * Cch, (long long)Nn * Cch);

    // 2a) gx = msg @ gru_W + gru_b[0]                 (K=512 -> T=16)
    gemm_tf32<<<dim3(C3 / BN, MR / BM, 1), blk, SMEM_BYTES>>>(
        msg, W, gx, gb, Cch, Cch, C3, C3, 0, 0, 0);

    // 2b) gh = annotations @ gru_U + gru_b[1]
    gemm_tf32<<<dim3(C3 / BN, MR / BM, 1), blk, SMEM_BYTES>>>(
        ann, U, gh, gb + C3, Cch, Cch, C3, C3, 0, 0, 0);

    // 3) gates -> hnew
    gates_kernel<<<(MR * (Cch / 4)) / 256, blk>>>(ann);

    // 4) out = hnew @ dense_W + dense_b
    gemm_tf32<<<dim3(Oo / BN, MR / BM, 1), blk, SMEM_BYTES>>>(
        hnew, dW, out, db, Cch, Cch, Oo, Oo, 0, 0, 0);
}

// round 9
// speedup vs baseline: 1.5064x; 1.0376x over previous
#include <cuda_runtime.h>
#include <cstdint>
#include <cstddef>

// ---------------------------------------------------------------- shapes
constexpr int Bb  = 128;
constexpr int Nn  = 256;
constexpr int Cch = 512;
constexpr int Oo  = 256;
constexpr int MR  = Bb * Nn;   // 32768
constexpr int C3  = 3 * Cch;   // 1536
constexpr int C2  = 2 * Cch;   // 1024

// ---------------------------------------------------------------- scratch
__device__ float g_msg [(size_t)MR * Cch];   //  64 MB
__device__ float g_gzr [(size_t)MR * C2];    // 134 MB  (xz+hz | xr+hr)
__device__ float g_xh  [(size_t)MR * Cch];   //  67 MB
__device__ float g_hnew[(size_t)MR * Cch];   //  64 MB

// ---------------------------------------------------------------- helpers
__device__ __forceinline__ uint32_t smem_u32(const void* p) {
    uint32_t a;
    asm("{ .reg .u64 t; cvta.to.shared.u64 t, %1; cvt.u32.u64 %0, t; }" : "=r"(a) : "l"(p));
    return a;
}
__device__ __forceinline__ uint32_t f2tf(float f) {
    uint32_t u;
    asm("cvt.rna.tf32.f32 %0, %1;" : "=r"(u) : "f"(f));
    return u;
}
__device__ __forceinline__ void cp16(uint32_t saddr, const float* g) {
    asm volatile("cp.async.cg.shared.global [%0], [%1], 16;" :: "r"(saddr), "l"(g));
}
#define CP_COMMIT() asm volatile("cp.async.commit_group;" ::: "memory")
#define CP_WAIT1()  asm volatile("cp.async.wait_group 1;"  ::: "memory")

__device__ __forceinline__ void mma8(float* c, const uint32_t* a, const uint32_t* b) {
    asm volatile(
        "mma.sync.aligned.m16n8k8.row.col.f32.tf32.tf32.f32 "
        "{%0,%1,%2,%3}, {%4,%5,%6,%7}, {%8,%9}, {%0,%1,%2,%3};\n"
        : "+f"(c[0]), "+f"(c[1]), "+f"(c[2]), "+f"(c[3])
        : "r"(a[0]), "r"(a[1]), "r"(a[2]), "r"(a[3]),
          "r"(b[0]), "r"(b[1]));
}
__device__ __forceinline__ float sigf(float x) { return 1.f / (1.f + __expf(-x)); }

// ---------------------------------------------------------------- GEMM
// CTA 128x128, 8 warps (2x4), warp 64x32, BK=32, 3-stage cp.async, 2 CTA/SM.
// DUAL : C = A1@B1 + A2@B2 + bias1 + bias2   (two K-passes, shared lda/ldb)
// GATES: C(=hnew) = gru_gate(gzr, xh, acc+bias1, ann) fused epilogue
constexpr int BM = 128, BN = 128, BK = 32;
constexpr int ASTR = BK + 4;    // 36
constexpr int BSTR = BN + 8;    // 136
constexpr int STAGES = 3;
constexpr int ASZ = BM * ASTR;
constexpr int BSZ = BK * BSTR;
constexpr int SMEM_BYTES = STAGES * (ASZ + BSZ) * 4;   // 107520 B

template<bool DUAL, bool GATES>
__global__ __launch_bounds__(256, 2)
void gemm_k(const float* __restrict__ A1, const float* __restrict__ B1, int T1,
            const float* __restrict__ A2, const float* __restrict__ B2, int T2,
            float* __restrict__ C,
            const float* __restrict__ bias1, const float* __restrict__ bias2,
            int lda, int ldb, int ldc,
            long long sA, long long sB, long long sC,
            const float* __restrict__ gzr, const float* __restrict__ xh,
            const float* __restrict__ ann)
{
    extern __shared__ float sm[];
    float* As = sm;
    float* Bs = sm + STAGES * ASZ;
    const uint32_t sbA = smem_u32(As);
    const uint32_t sbB = smem_u32(Bs);

    A1 += (long long)blockIdx.z * sA;
    B1 += (long long)blockIdx.z * sB;
    C  += (long long)blockIdx.z * sC;

    const int tid  = threadIdx.x;
    const int lane = tid & 31;
    const int warp = tid >> 5;
    const int wm   = warp >> 2;
    const int wn   = warp & 3;
    const int row0 = blockIdx.y * BM;
    const int col0 = blockIdx.x * BN;

    const int arow = tid >> 3;            // 0..31 (+32i)
    const int acol = (tid & 7) * 4;
    const int brow = tid >> 5;            // 0..7  (+8i)
    const int bcol = (tid & 31) * 4;

    const float* aG1 = A1 + (size_t)(row0 + arow) * lda + acol;
    const float* bG1 = B1 + (size_t)brow * ldb + (col0 + bcol);
    const float* aG2 = DUAL ? A2 + (size_t)(row0 + arow) * lda + acol : nullptr;
    const float* bG2 = DUAL ? B2 + (size_t)brow * ldb + (col0 + bcol) : nullptr;

    uint32_t aS[4], bS[4];
#pragma unroll
    for (int i = 0; i < 4; i++) {
        aS[i] = sbA + (uint32_t)((arow + 32 * i) * ASTR + acol) * 4u;
        bS[i] = sbB + (uint32_t)((brow + 8 * i) * BSTR + bcol) * 4u;
    }

    auto issue = [&](int kt, int s) {
        const float *ag, *bg;
        if (DUAL && kt >= T1) {
            const int k2 = kt - T1;
            ag = aG2 + (size_t)k2 * BK;
            bg = bG2 + (size_t)k2 * BK * ldb;
        } else {
            ag = aG1 + (size_t)kt * BK;
            bg = bG1 + (size_t)kt * BK * ldb;
        }
#pragma unroll
        for (int i = 0; i < 4; i++)
            cp16(aS[i] + s * (ASZ * 4), ag + (size_t)(32 * i) * lda);
#pragma unroll
        for (int i = 0; i < 4; i++)
            cp16(bS[i] + s * (BSZ * 4), bg + (size_t)(8 * i) * ldb);
    };

    const int T = DUAL ? (T1 + T2) : T1;

    float acc[4][4][4];
#pragma unroll
    for (int mi = 0; mi < 4; mi++)
#pragma unroll
        for (int ni = 0; ni < 4; ni++)
#pragma unroll
            for (int r = 0; r < 4; r++) acc[mi][ni][r] = 0.f;

    issue(0, 0); CP_COMMIT();
    issue(1, 1); CP_COMMIT();

    int use_s = 0, fill_s = 2;
    for (int kt = 0; kt < T; kt++) {
        CP_WAIT1();
        __syncthreads();

        if (kt + 2 < T) issue(kt + 2, fill_s);
        CP_COMMIT();

        const float* as = As + use_s * ASZ;
        const float* bs = Bs + use_s * BSZ;
#pragma unroll
        for (int kk = 0; kk < BK; kk += 8) {
            uint32_t af[4][4], bf[4][2];
#pragma unroll
            for (int mi = 0; mi < 4; mi++) {
                const int r  = wm * 64 + mi * 16 + (lane >> 2);
                const int cc = kk + (lane & 3);
                af[mi][0] = f2tf(as[ r      * ASTR + cc    ]);
                af[mi][1] = f2tf(as[(r + 8) * ASTR + cc    ]);
                af[mi][2] = f2tf(as[ r      * ASTR + cc + 4]);
                af[mi][3] = f2tf(as[(r + 8) * ASTR + cc + 4]);
            }
#pragma unroll
            for (int ni = 0; ni < 4; ni++) {
                const int cc = wn * 32 + ni * 8 + (lane >> 2);
                const int kr = kk + (lane & 3);
                bf[ni][0] = f2tf(bs[ kr      * BSTR + cc]);
                bf[ni][1] = f2tf(bs[(kr + 4) * BSTR + cc]);
            }
#pragma unroll
            for (int mi = 0; mi < 4; mi++)
#pragma unroll
                for (int ni = 0; ni < 4; ni++)
                    mma8(acc[mi][ni], af[mi], bf[ni]);
        }

        if (++use_s  == STAGES) use_s  = 0;
        if (++fill_s == STAGES) fill_s = 0;
    }

    // ---------------- epilogue ----------------
#pragma unroll
    for (int mi = 0; mi < 4; mi++) {
        const int gr = row0 + wm * 64 + mi * 16 + (lane >> 2);
#pragma unroll
        for (int ni = 0; ni < 4; ni++) {
            const int gc = col0 + wn * 32 + ni * 8 + (lane & 3) * 2;
#pragma unroll
            for (int half = 0; half < 2; half++) {
                const int r  = gr + half * 8;
                float v0 = acc[mi][ni][half * 2 + 0] + __ldg(&bias1[gc]);
                float v1 = acc[mi][ni][half * 2 + 1] + __ldg(&bias1[gc + 1]);
                if (DUAL) {
                    v0 += __ldg(&bias2[gc]);
                    v1 += __ldg(&bias2[gc + 1]);
                }
                if (GATES) {
                    // v = hh (pre-activation).  channel = gc (N==Cch here)
                    const float2 zs = *(const float2*)&gzr[(size_t)r * C2 + gc];
                    const float2 rs = *(const float2*)&gzr[(size_t)r * C2 + Cch + gc];
                    const float2 xv = *(const float2*)&xh [(size_t)r * Cch + gc];
                    const float2 hv = *(const float2*)&ann[(size_t)r * Cch + gc];
                    const float z0 = sigf(zs.x), z1 = sigf(zs.y);
                    const float r0 = sigf(rs.x), r1 = sigf(rs.y);
                    const float h0 = tanhf(xv.x + r0 * v0);
                    const float h1 = tanhf(xv.y + r1 * v1);
                    v0 = z0 * hv.x + (1.f - z0) * h0;
                    v1 = z1 * hv.y + (1.f - z1) * h1;
                }
                *(float2*)&C[(size_t)r * ldc + gc] = make_float2(v0, v1);
            }
        }
    }
}

// ---------------------------------------------------------------- launch
extern "C" void kernel_launch(void* const* d_in, const int* in_sizes, int n_in,
                              void* d_out, int out_size)
{
    const float* adj = (const float*)d_in[0];
    const float* ann = (const float*)d_in[1];
    const float* gcb = (const float*)d_in[2];
    const float* W   = (const float*)d_in[3];  // [512,1536]
    const float* U   = (const float*)d_in[4];  // [512,1536]
    const float* gb  = (const float*)d_in[5];  // [2,1536]
    const float* dW  = (const float*)d_in[6];  // [512,256]
    const float* db  = (const float*)d_in[7];  // [256]
    float* out = (float*)d_out;

    float *msg, *gzr, *xh, *hnew;
    cudaGetSymbolAddress((void**)&msg,  g_msg);
    cudaGetSymbolAddress((void**)&gzr,  g_gzr);
    cudaGetSymbolAddress((void**)&xh,   g_xh);
    cudaGetSymbolAddress((void**)&hnew, g_hnew);

    cudaFuncSetAttribute(gemm_k<false,false>, cudaFuncAttributeMaxDynamicSharedMemorySize, SMEM_BYTES);
    cudaFuncSetAttribute(gemm_k<true, false>, cudaFuncAttributeMaxDynamicSharedMemorySize, SMEM_BYTES);
    cudaFuncSetAttribute(gemm_k<false,true >, cudaFuncAttributeMaxDynamicSharedMemorySize, SMEM_BYTES);

    const dim3 blk(256);

    // 1) msg = bmm(adjacent, annotations) + gc_bias        (K=256 -> T=8)
    gemm_k<false,false><<<dim3(Cch / BN, Nn / BM, Bb), blk, SMEM_BYTES>>>(
        adj, ann, Nn / BK, nullptr, nullptr, 0,
        msg, gcb, nullptr,
        Nn, Cch, Cch,
        (long long)Nn * Nn, (long long)Nn * Cch, (long long)Nn * Cch,
        nullptr, nullptr, nullptr);

    // 2) gzr = msg@W[:,0:1024] + ann@U[:,0:1024] + b0 + b1 (dual K: 16+16)
    gemm_k<true,false><<<dim3(C2 / BN, MR / BM, 1), blk, SMEM_BYTES>>>(
        msg, W, Cch / BK, ann, U, Cch / BK,
        gzr, gb, gb + C3,
        Cch, C3, C2, 0, 0, 0,
        nullptr, nullptr, nullptr);

    // 3) xh = msg@W[:,1024:1536] + b0[1024:]
    gemm_k<false,false><<<dim3(Cch / BN, MR / BM, 1), blk, SMEM_BYTES>>>(
        msg, W + C2, Cch / BK, nullptr, nullptr, 0,
        xh, gb + C2, nullptr,
        Cch, C3, Cch, 0, 0, 0,
        nullptr, nullptr, nullptr);

    // 4) hnew = gate( gzr, xh, ann@U[:,1024:]+b1[1024:], ann )  (fused epilogue)
    gemm_k<false,true><<<dim3(Cch / BN, MR / BM, 1), blk, SMEM_BYTES>>>(
        ann, U + C2, Cch / BK, nullptr, nullptr, 0,
        hnew, gb + C3 + C2, nullptr,
        Cch, C3, Cch, 0, 0, 0,
        gzr, xh, ann);

    // 5) out = hnew @ dense_W + dense_b
    gemm_k<false,false><<<dim3(Oo / BN, MR / BM, 1), blk, SMEM_BYTES>>>(
        hnew, dW, Cch / BK, nullptr, nullptr, 0,
        out, db, nullptr,
        Cch, Oo, Oo, 0, 0, 0,
        nullptr, nullptr, nullptr);
}